// round 17
// baseline (speedup 1.0000x reference)
#include <cuda_runtime.h>
#include <cuda_bf16.h>
#include <cstdint>

// TriplaneDecoder R16 = R15 (371us) with B-fragment loads shared across the
// two m-tiles (loop inversion: B outermost, both tiles' MMAs inside) ->
// B LDS.128 halved (96 -> 48 per warp), -6 L1 wavefronts/point.
// Gather = R6 warp-coop coalesced. Output: [c (N*3), sigma (N)].

#define GRID_N   512
#define NF       32
#define HID      64
#define TPB      256
#define FSTR     36            // feat tile row stride (col 32 = mask flag)
#define FULLMASK 0xffffffffu

__device__ __forceinline__ uint32_t bfp(float a, float b) {
    unsigned short ha = __bfloat16_as_ushort(__float2bfloat16(a));
    unsigned short hb = __bfloat16_as_ushort(__float2bfloat16(b));
    return (uint32_t)ha | ((uint32_t)hb << 16);
}
__device__ __forceinline__ float bfres(float a) {
    return a - __bfloat162float(__float2bfloat16(a));
}

#define MMA_BF16(d0, d1, d2, d3, a0, a1, a2, a3, b0, b1)                      \
    asm volatile("mma.sync.aligned.m16n8k16.row.col.f32.bf16.bf16.f32 "       \
        "{%0,%1,%2,%3}, {%4,%5,%6,%7}, {%8,%9}, {%0,%1,%2,%3};"               \
        : "+f"(d0), "+f"(d1), "+f"(d2), "+f"(d3)                              \
        : "r"(a0), "r"(a1), "r"(a2), "r"(a3), "r"(b0), "r"(b1))

extern __shared__ float smemDyn[];   // feat tile: 8 warps * 32 * FSTR floats

__global__ __launch_bounds__(TPB, 2)
void triplane_decoder_kernel(const float* __restrict__ x,
                             const float* __restrict__ pzh,
                             const float* __restrict__ phw,
                             const float* __restrict__ pzw,
                             const float* __restrict__ W1,
                             const float* __restrict__ W2,
                             const float* __restrict__ W3,
                             float* __restrict__ out, int n) {
    // B fragments, hi/lo interleaved: {hi_r0, hi_r1, lo_r0, lo_r1} per lane
    __shared__ __align__(16) uint4 sB1[2 * 8 * 32];   // [kt][nt][lane]
    __shared__ __align__(16) uint4 sB2[4 * 8 * 32];
    __shared__ __align__(16) float sW3[HID * 4];

    int tid  = threadIdx.x;
    int lane = tid & 31;
    int warp = tid >> 5;
    int g    = lane >> 2;      // fragment row group
    int t    = lane & 3;       // fragment thread-in-group

    // ---- build B fragments once per CTA ----
    for (int idx = tid; idx < 2 * 8 * 32; idx += TPB) {
        int l = idx & 31, nt = (idx >> 5) & 7, kt = idx >> 8;
        int lg = l >> 2, lt = l & 3;
        int nn = 8 * nt + lg;
        int k0 = 16 * kt + 2 * lt;
        float w00 = W1[k0 * HID + nn],       w01 = W1[(k0 + 1) * HID + nn];
        float w10 = W1[(k0 + 8) * HID + nn], w11 = W1[(k0 + 9) * HID + nn];
        sB1[idx] = make_uint4(bfp(w00, w01), bfp(w10, w11),
                              bfp(bfres(w00), bfres(w01)), bfp(bfres(w10), bfres(w11)));
    }
    for (int idx = tid; idx < 4 * 8 * 32; idx += TPB) {
        int l = idx & 31, nt = (idx >> 5) & 7, kt = idx >> 8;
        int lg = l >> 2, lt = l & 3;
        int nn = 8 * nt + lg;
        int k0 = 16 * kt + 2 * lt;
        float w00 = W2[k0 * HID + nn],       w01 = W2[(k0 + 1) * HID + nn];
        float w10 = W2[(k0 + 8) * HID + nn], w11 = W2[(k0 + 9) * HID + nn];
        sB2[idx] = make_uint4(bfp(w00, w01), bfp(w10, w11),
                              bfp(bfres(w00), bfres(w01)), bfp(bfres(w10), bfres(w11)));
    }
    for (int idx = tid; idx < HID * 4; idx += TPB) sW3[idx] = W3[idx];
    __syncthreads();

    // ---- per-point coords + gather setup (own point = lane) ----
    int i0 = blockIdx.x * TPB + tid;
    int i = min(i0, n - 1);
    float x0 = x[3 * i + 0];
    float x1 = x[3 * i + 1];
    float x2 = x[3 * i + 2];
    bool mask = (fabsf(x0) < 1.0f) && (fabsf(x1) < 1.0f) && (fabsf(x2) < 1.0f);

    float cus[3] = {x0, x1, x2};
    float cvs[3] = {x1, x2, x0};
    unsigned off4[3][4];
    float    wgt[3][4];
    #pragma unroll
    for (int p = 0; p < 3; p++) {
        const float S = 0.5f * (float)(GRID_N - 1);
        float u = fminf(fmaxf(fmaf(cus[p], S, S), 0.0f), (float)(GRID_N - 1));
        float v = fminf(fmaxf(fmaf(cvs[p], S, S), 0.0f), (float)(GRID_N - 1));
        float fu = floorf(u), fv = floorf(v);
        int u0 = (int)fu, v0 = (int)fv;
        int u1 = min(u0 + 1, GRID_N - 1);
        int v1 = min(v0 + 1, GRID_N - 1);
        float wu = u - fu, wv = v - fv;
        wgt[p][0] = (1.0f - wu) * (1.0f - wv);
        wgt[p][1] = (1.0f - wu) * wv;
        wgt[p][2] = wu * (1.0f - wv);
        wgt[p][3] = wu * wv;
        off4[p][0] = (unsigned)((u0 * GRID_N + v0) * (NF / 4));
        off4[p][1] = (unsigned)((u0 * GRID_N + v1) * (NF / 4));
        off4[p][2] = (unsigned)((u1 * GRID_N + v0) * (NF / 4));
        off4[p][3] = (unsigned)((u1 * GRID_N + v1) * (NF / 4));
    }

    // ---- warp-cooperative coalesced gather (R6 verbatim) ----
    const float4* bases[3] = {(const float4*)pzh, (const float4*)phw, (const float4*)pzw};
    float* fWarp = smemDyn + warp * 32 * FSTR;
    int jj = lane >> 3;
    int kk = lane & 7;
    #pragma unroll
    for (int tt = 0; tt < 8; tt++) {
        int src = 4 * tt + jj;
        float4 acc;
        #pragma unroll
        for (int p = 0; p < 3; p++) {
            float4 pf;
            #pragma unroll
            for (int c = 0; c < 4; c++) {
                unsigned o = __shfl_sync(FULLMASK, off4[p][c], src);
                float    w = __shfl_sync(FULLMASK, wgt[p][c], src);
                float4 d = __ldg(bases[p] + o + kk);
                if (c == 0) {
                    pf.x = w * d.x; pf.y = w * d.y; pf.z = w * d.z; pf.w = w * d.w;
                } else {
                    pf.x = fmaf(w, d.x, pf.x); pf.y = fmaf(w, d.y, pf.y);
                    pf.z = fmaf(w, d.z, pf.z); pf.w = fmaf(w, d.w, pf.w);
                }
            }
            if (p == 0) acc = pf;
            else { acc.x *= pf.x; acc.y *= pf.y; acc.z *= pf.z; acc.w *= pf.w; }
        }
        *(float4*)(fWarp + src * FSTR + kk * 4) = acc;
    }
    fWarp[lane * FSTR + 32] = mask ? 1.0f : 0.0f;
    __syncwarp();

    // ---- tensor-core MLP: both 16-row tiles, B fragments loaded ONCE ----
    // A1 fragments (hi/lo) for both tiles
    uint32_t a1hi[2][2][4], a1lo[2][2][4];   // [mt][kt][r]
    #pragma unroll
    for (int mt = 0; mt < 2; mt++) {
        int base = 16 * mt;
        #pragma unroll
        for (int kt = 0; kt < 2; kt++) {
            float2 v0 = *(const float2*)(fWarp + (base + g)     * FSTR + 16 * kt + 2 * t);
            float2 v1 = *(const float2*)(fWarp + (base + g + 8) * FSTR + 16 * kt + 2 * t);
            float2 v2 = *(const float2*)(fWarp + (base + g)     * FSTR + 16 * kt + 8 + 2 * t);
            float2 v3 = *(const float2*)(fWarp + (base + g + 8) * FSTR + 16 * kt + 8 + 2 * t);
            a1hi[mt][kt][0] = bfp(v0.x, v0.y); a1lo[mt][kt][0] = bfp(bfres(v0.x), bfres(v0.y));
            a1hi[mt][kt][1] = bfp(v1.x, v1.y); a1lo[mt][kt][1] = bfp(bfres(v1.x), bfres(v1.y));
            a1hi[mt][kt][2] = bfp(v2.x, v2.y); a1lo[mt][kt][2] = bfp(bfres(v2.x), bfres(v2.y));
            a1hi[mt][kt][3] = bfp(v3.x, v3.y); a1lo[mt][kt][3] = bfp(bfres(v3.x), bfres(v3.y));
        }
    }

    // Layer 1 in nt-pairs for BOTH tiles; repack into layer-2 A fragments
    uint32_t a2hi[2][4][4], a2lo[2][4][4];   // [mt][kt2][r]
    #pragma unroll
    for (int q2 = 0; q2 < 4; q2++) {
        float d[2][8];
        #pragma unroll
        for (int mt = 0; mt < 2; mt++)
            #pragma unroll
            for (int q = 0; q < 8; q++) d[mt][q] = 0.0f;
        #pragma unroll
        for (int kt = 0; kt < 2; kt++) {
            uint4 bA = sB1[(kt * 8 + 2 * q2) * 32 + lane];
            #pragma unroll
            for (int mt = 0; mt < 2; mt++) {
                MMA_BF16(d[mt][0], d[mt][1], d[mt][2], d[mt][3],
                         a1hi[mt][kt][0], a1hi[mt][kt][1], a1hi[mt][kt][2], a1hi[mt][kt][3], bA.x, bA.y);
                MMA_BF16(d[mt][0], d[mt][1], d[mt][2], d[mt][3],
                         a1hi[mt][kt][0], a1hi[mt][kt][1], a1hi[mt][kt][2], a1hi[mt][kt][3], bA.z, bA.w);
                MMA_BF16(d[mt][0], d[mt][1], d[mt][2], d[mt][3],
                         a1lo[mt][kt][0], a1lo[mt][kt][1], a1lo[mt][kt][2], a1lo[mt][kt][3], bA.x, bA.y);
            }
            uint4 bB = sB1[(kt * 8 + 2 * q2 + 1) * 32 + lane];
            #pragma unroll
            for (int mt = 0; mt < 2; mt++) {
                MMA_BF16(d[mt][4], d[mt][5], d[mt][6], d[mt][7],
                         a1hi[mt][kt][0], a1hi[mt][kt][1], a1hi[mt][kt][2], a1hi[mt][kt][3], bB.x, bB.y);
                MMA_BF16(d[mt][4], d[mt][5], d[mt][6], d[mt][7],
                         a1hi[mt][kt][0], a1hi[mt][kt][1], a1hi[mt][kt][2], a1hi[mt][kt][3], bB.z, bB.w);
                MMA_BF16(d[mt][4], d[mt][5], d[mt][6], d[mt][7],
                         a1lo[mt][kt][0], a1lo[mt][kt][1], a1lo[mt][kt][2], a1lo[mt][kt][3], bB.x, bB.y);
            }
        }
        #pragma unroll
        for (int mt = 0; mt < 2; mt++) {
            float h0 = fmaxf(d[mt][0], 0.0f), h1 = fmaxf(d[mt][1], 0.0f);
            float h2 = fmaxf(d[mt][2], 0.0f), h3 = fmaxf(d[mt][3], 0.0f);
            float h4 = fmaxf(d[mt][4], 0.0f), h5 = fmaxf(d[mt][5], 0.0f);
            float h6 = fmaxf(d[mt][6], 0.0f), h7 = fmaxf(d[mt][7], 0.0f);
            a2hi[mt][q2][0] = bfp(h0, h1); a2lo[mt][q2][0] = bfp(bfres(h0), bfres(h1));
            a2hi[mt][q2][1] = bfp(h2, h3); a2lo[mt][q2][1] = bfp(bfres(h2), bfres(h3));
            a2hi[mt][q2][2] = bfp(h4, h5); a2lo[mt][q2][2] = bfp(bfres(h4), bfres(h5));
            a2hi[mt][q2][3] = bfp(h6, h7); a2lo[mt][q2][3] = bfp(bfres(h6), bfres(h7));
        }
    }

    // Layer 2 + fused layer 3 partials, B loaded once per (nt,kt)
    float o[2][8];
    #pragma unroll
    for (int mt = 0; mt < 2; mt++)
        #pragma unroll
        for (int q = 0; q < 8; q++) o[mt][q] = 0.0f;

    #pragma unroll
    for (int nt = 0; nt < 8; nt++) {
        float d[2][4];
        #pragma unroll
        for (int mt = 0; mt < 2; mt++)
            #pragma unroll
            for (int q = 0; q < 4; q++) d[mt][q] = 0.0f;
        #pragma unroll
        for (int kt = 0; kt < 4; kt++) {
            uint4 b = sB2[(kt * 8 + nt) * 32 + lane];
            #pragma unroll
            for (int mt = 0; mt < 2; mt++) {
                MMA_BF16(d[mt][0], d[mt][1], d[mt][2], d[mt][3],
                         a2hi[mt][kt][0], a2hi[mt][kt][1], a2hi[mt][kt][2], a2hi[mt][kt][3], b.x, b.y);
                MMA_BF16(d[mt][0], d[mt][1], d[mt][2], d[mt][3],
                         a2hi[mt][kt][0], a2hi[mt][kt][1], a2hi[mt][kt][2], a2hi[mt][kt][3], b.z, b.w);
                MMA_BF16(d[mt][0], d[mt][1], d[mt][2], d[mt][3],
                         a2lo[mt][kt][0], a2lo[mt][kt][1], a2lo[mt][kt][2], a2lo[mt][kt][3], b.x, b.y);
            }
        }
        int c = 8 * nt + 2 * t;
        float4 w3a = *(const float4*)(sW3 + c * 4);
        float4 w3b = *(const float4*)(sW3 + (c + 1) * 4);
        #pragma unroll
        for (int mt = 0; mt < 2; mt++) {
            float h0 = fmaxf(d[mt][0], 0.0f), h1 = fmaxf(d[mt][1], 0.0f);
            float h2 = fmaxf(d[mt][2], 0.0f), h3 = fmaxf(d[mt][3], 0.0f);
            o[mt][0] = fmaf(h0, w3a.x, fmaf(h1, w3b.x, o[mt][0]));
            o[mt][1] = fmaf(h0, w3a.y, fmaf(h1, w3b.y, o[mt][1]));
            o[mt][2] = fmaf(h0, w3a.z, fmaf(h1, w3b.z, o[mt][2]));
            o[mt][3] = fmaf(h0, w3a.w, fmaf(h1, w3b.w, o[mt][3]));
            o[mt][4] = fmaf(h2, w3a.x, fmaf(h3, w3b.x, o[mt][4]));
            o[mt][5] = fmaf(h2, w3a.y, fmaf(h3, w3b.y, o[mt][5]));
            o[mt][6] = fmaf(h2, w3a.z, fmaf(h3, w3b.z, o[mt][6]));
            o[mt][7] = fmaf(h2, w3a.w, fmaf(h3, w3b.w, o[mt][7]));
        }
    }
    #pragma unroll
    for (int off = 1; off <= 2; off <<= 1)
        #pragma unroll
        for (int mt = 0; mt < 2; mt++)
            #pragma unroll
            for (int q = 0; q < 8; q++)
                o[mt][q] += __shfl_xor_sync(FULLMASK, o[mt][q], off);

    if (t < 2) {
        #pragma unroll
        for (int mt = 0; mt < 2; mt++) {
            int prow = 16 * mt + g + 8 * t;
            const float* ov = o[mt] + 4 * t;
            int p = blockIdx.x * TPB + warp * 32 + prow;
            if (p < n) {
                bool m = fWarp[prow * FSTR + 32] > 0.5f;
                float c0 = m ? 1.0f / (1.0f + __expf(-ov[0])) : 0.0f;
                float c1 = m ? 1.0f / (1.0f + __expf(-ov[1])) : 0.0f;
                float c2 = m ? 1.0f / (1.0f + __expf(-ov[2])) : 0.0f;
                float sg = m ? __expf(ov[3]) : 0.0f;
                out[3 * p + 0] = c0;
                out[3 * p + 1] = c1;
                out[3 * p + 2] = c2;
                out[3 * n + p] = sg;
            }
        }
    }
}

extern "C" void kernel_launch(void* const* d_in, const int* in_sizes, int n_in,
                              void* d_out, int out_size) {
    const float* x   = (const float*)d_in[0];  // [N,3]
    const float* pzh = (const float*)d_in[1];  // [512,512,32]
    const float* phw = (const float*)d_in[2];
    const float* pzw = (const float*)d_in[3];
    const float* W1  = (const float*)d_in[4];  // [32,64]
    const float* W2  = (const float*)d_in[5];  // [64,64]
    const float* W3  = (const float*)d_in[6];  // [64,4]
    float* out = (float*)d_out;

    int n = in_sizes[0] / 3;
    int blocks = (n + TPB - 1) / TPB;

    size_t smem = (size_t)(8 * 32 * FSTR) * sizeof(float);
    cudaFuncSetAttribute(triplane_decoder_kernel,
                         cudaFuncAttributeMaxDynamicSharedMemorySize, (int)smem);
    triplane_decoder_kernel<<<blocks, TPB, smem>>>(x, pzh, phw, pzw, W1, W2, W3, out, n);
}